// round 15
// baseline (speedup 1.0000x reference)
#include <cuda_runtime.h>
#include <cuda_bf16.h>

// Welford running mean/variance over batch dim of x: (B, C, H, W), B=256, CHW=262144.
// One scalar thread per spatial position (262,144 threads).
//
// R15 = polished champion family (R4/R13): dual half-batch Welford streams with
// exact Chan merge, shared-memory reciprocal tables (no MUFU/counters in loop),
// unroll 8, merge constants hoisted. regs=32 / full occupancy / 6 TB/s wall.
// Session model: kernel floor ~82us (mixed-R/W bandwidth wall); dual-stream +
// lean-issue shape holds its time best under the timed loop's sustained clocks.
//
// Output layout (float32, concatenated):
//   [0, B*CHW) : x passthrough | [+0,+CHW): m | [+CHW,+2CHW): s
//   [+2CHW,+3CHW): neuron_nonzero | [last]: n_samples + B

__global__ void __launch_bounds__(256) welford_dual_final(
    const float* __restrict__ x,
    const float* __restrict__ m_in,
    const float* __restrict__ s_in,
    const int*   __restrict__ nn_in,
    const int*   __restrict__ n_in,
    float*       __restrict__ out,
    int B, int CHW)
{
    __shared__ float invA_tab[128];
    __shared__ float invB_tab[128];

    const int H  = B >> 1;                 // 128
    const int n0 = n_in[0];

    // Thread-invariant reciprocal tables (same math as the reference recurrence).
    {
        int t = threadIdx.x;
        if (t < H) {
            invA_tab[t] = __fdividef(1.0f, (float)(n0 + t + 1));
            invB_tab[t] = __fdividef(1.0f, (float)(t + 1));
        }
    }
    __syncthreads();

    int p = blockIdx.x * blockDim.x + threadIdx.x;
    if (p >= CHW) return;

    const size_t step = (size_t)CHW;

    // Stream A continues the input state over b in [0, H);
    // Stream B runs standalone from zero over b in [H, B).
    float mA = m_in[p], sA = s_in[p];
    float mB = 0.0f,    sB = 0.0f;
    int   nnA = nn_in[p], nnB = 0;

    const float* xA = x + p;
    const float* xB = x + p + (size_t)H * step;
    float*       oA = out + p;
    float*       oB = out + p + (size_t)H * step;

    #pragma unroll 8
    for (int b = 0; b < H; ++b) {
        size_t off = (size_t)b * step;
        float va = xA[off];
        float vb = xB[off];
        oA[off] = va;                        // passthrough
        oB[off] = vb;

        nnA += (va != 0.0f);
        nnB += (vb != 0.0f);

        float iA = invA_tab[b];              // broadcast LDS (conflict-free)
        float iB = invB_tab[b];

        float om;
        om = mA; mA += (va - mA) * iA; sA += (va - mA) * (va - om);
        om = mB; mB += (vb - mB) * iB; sB += (vb - mB) * (vb - om);
    }

    // Exact Chan merge: A carries n0+H samples, B carries H samples.
    // All weights are thread-invariant.
    const float nAf  = (float)(n0 + H);
    const float nBf  = (float)H;
    const float invT = __fdividef(1.0f, nAf + nBf);
    const float wB   = nBf * invT;           // nB / nT
    const float wAB  = nAf * nBf * invT;     // nA*nB / nT

    float d  = mB - mA;
    float m  = mA + d * wB;
    float s  = sA + sB + d * d * wAB;
    int   nn = nnA + nnB;

    size_t base = (size_t)B * step;
    out[base + p]            = m;
    out[base + step + p]     = s;
    out[base + 2 * step + p] = (float)nn;
    if (p == 0) {
        out[base + 3 * step] = (float)(n0 + B);
    }
}

extern "C" void kernel_launch(void* const* d_in, const int* in_sizes, int n_in,
                              void* d_out, int out_size)
{
    const float* x  = (const float*)d_in[0];
    const float* m  = (const float*)d_in[1];
    const float* s  = (const float*)d_in[2];
    const int*   nn = (const int*)d_in[3];
    const int*   n  = (const int*)d_in[4];
    float* out = (float*)d_out;

    const int CHW = in_sizes[1];          // 262144
    const int B   = in_sizes[0] / CHW;    // 256

    const int threads = 256;
    const int blocks = (CHW + threads - 1) / threads;  // 1024
    welford_dual_final<<<blocks, threads>>>(x, m, s, nn, n, out, B, CHW);
}

// round 16
// speedup vs baseline: 1.7809x; 1.7809x over previous
#include <cuda_runtime.h>
#include <cuda_bf16.h>

// Welford running mean/variance over batch dim of x: (B, C, H, W), B=256, CHW=262144.
// 262,144 scalar threads (one per spatial position).
// SESSION CHAMPION (R4, bench 92.2us): each thread runs TWO independent Welford
// streams over the two batch halves (doubling loads-in-flight per warp at the
// default 32-reg / full-occupancy point), merged exactly with Chan's formula.
// Resubmitted verbatim after R15's unroll-8 regression.
//
// Output layout (float32, concatenated):
//   [0, B*CHW)     : x passthrough
//   [+0, +CHW)     : m
//   [+CHW, +2CHW)  : s
//   [+2CHW, +3CHW) : neuron_nonzero (int -> float)
//   [last]         : n_samples + B

__global__ void __launch_bounds__(256) welford_kernel_2s(
    const float* __restrict__ x,
    const float* __restrict__ m_in,
    const float* __restrict__ s_in,
    const int*   __restrict__ nn_in,
    const int*   __restrict__ n_in,
    float*       __restrict__ out,
    int B, int CHW)
{
    int p = blockIdx.x * blockDim.x + threadIdx.x;
    if (p >= CHW) return;

    const int H  = B >> 1;              // 128
    const int n0 = n_in[0];

    // Stream A: continues the input state over b = 0..H-1
    float mA = m_in[p];
    float sA = s_in[p];
    int   nnA = nn_in[p];

    // Stream B: standalone Welford from zero over b = H..B-1
    float mB = 0.0f, sB = 0.0f;
    int   nnB = 0;

    const float* xpA = x + p;
    const float* xpB = x + p + (size_t)H * CHW;
    float*       opA = out + p;
    float*       opB = out + p + (size_t)H * CHW;

    #pragma unroll 4
    for (int b = 0; b < H; ++b) {
        float xa = xpA[(size_t)b * CHW];
        float xb = xpB[(size_t)b * CHW];
        opA[(size_t)b * CHW] = xa;          // passthrough
        opB[(size_t)b * CHW] = xb;

        nnA += (xa != 0.0f);
        nnB += (xb != 0.0f);

        float invA = __fdividef(1.0f, (float)(n0 + b + 1));
        float invB = __fdividef(1.0f, (float)(b + 1));

        float om;
        om = mA; mA += (xa - mA) * invA; sA += (xa - mA) * (xa - om);
        om = mB; mB += (xb - mB) * invB; sB += (xb - mB) * (xb - om);
    }

    // Chan merge: A holds n0+H samples of weight, B holds H samples.
    float nAf = (float)(n0 + H);
    float nBf = (float)H;
    float nTf = nAf + nBf;
    float invT = __fdividef(1.0f, nTf);
    float d  = mB - mA;
    float m  = mA + d * (nBf * invT);
    float s  = sA + sB + d * d * (nAf * nBf * invT);
    int   nn = nnA + nnB;

    size_t base = (size_t)B * (size_t)CHW;
    out[base + p]                    = m;
    out[base + (size_t)CHW + p]      = s;
    out[base + 2 * (size_t)CHW + p]  = (float)nn;
    if (p == 0) {
        out[base + 3 * (size_t)CHW] = (float)(n0 + B);
    }
}

extern "C" void kernel_launch(void* const* d_in, const int* in_sizes, int n_in,
                              void* d_out, int out_size)
{
    const float* x  = (const float*)d_in[0];
    const float* m  = (const float*)d_in[1];
    const float* s  = (const float*)d_in[2];
    const int*   nn = (const int*)d_in[3];
    const int*   n  = (const int*)d_in[4];
    float* out = (float*)d_out;

    const int CHW = in_sizes[1];          // 262144
    const int B   = in_sizes[0] / CHW;    // 256

    const int threads = 256;
    const int blocks = (CHW + threads - 1) / threads;  // 1024
    welford_kernel_2s<<<blocks, threads>>>(x, m, s, nn, n, out, B, CHW);
}

// round 17
// speedup vs baseline: 1.7915x; 1.0059x over previous
#include <cuda_runtime.h>
#include <cuda_bf16.h>

// Welford running mean/variance over batch dim of x: (B, C, H, W), B=256, CHW=262144.
// 262,144 scalar threads (one per spatial position).
// R17 = session champion R4 (dual half-batch Welford streams + exact Chan merge,
// regs=32, bench 92.0/92.2 across two runs) with the ONLY untested launch
// parameter changed: block size 256 -> 128 (2048 blocks). Same total threads,
// same per-thread code; finer occupancy quantization + smaller wave tail.
//
// Output layout (float32, concatenated):
//   [0, B*CHW)     : x passthrough
//   [+0, +CHW)     : m
//   [+CHW, +2CHW)  : s
//   [+2CHW, +3CHW) : neuron_nonzero (int -> float)
//   [last]         : n_samples + B

__global__ void __launch_bounds__(128) welford_kernel_2s(
    const float* __restrict__ x,
    const float* __restrict__ m_in,
    const float* __restrict__ s_in,
    const int*   __restrict__ nn_in,
    const int*   __restrict__ n_in,
    float*       __restrict__ out,
    int B, int CHW)
{
    int p = blockIdx.x * blockDim.x + threadIdx.x;
    if (p >= CHW) return;

    const int H  = B >> 1;              // 128
    const int n0 = n_in[0];

    // Stream A: continues the input state over b = 0..H-1
    float mA = m_in[p];
    float sA = s_in[p];
    int   nnA = nn_in[p];

    // Stream B: standalone Welford from zero over b = H..B-1
    float mB = 0.0f, sB = 0.0f;
    int   nnB = 0;

    const float* xpA = x + p;
    const float* xpB = x + p + (size_t)H * CHW;
    float*       opA = out + p;
    float*       opB = out + p + (size_t)H * CHW;

    #pragma unroll 4
    for (int b = 0; b < H; ++b) {
        float xa = xpA[(size_t)b * CHW];
        float xb = xpB[(size_t)b * CHW];
        opA[(size_t)b * CHW] = xa;          // passthrough
        opB[(size_t)b * CHW] = xb;

        nnA += (xa != 0.0f);
        nnB += (xb != 0.0f);

        float invA = __fdividef(1.0f, (float)(n0 + b + 1));
        float invB = __fdividef(1.0f, (float)(b + 1));

        float om;
        om = mA; mA += (xa - mA) * invA; sA += (xa - mA) * (xa - om);
        om = mB; mB += (xb - mB) * invB; sB += (xb - mB) * (xb - om);
    }

    // Chan merge: A holds n0+H samples of weight, B holds H samples.
    float nAf = (float)(n0 + H);
    float nBf = (float)H;
    float nTf = nAf + nBf;
    float invT = __fdividef(1.0f, nTf);
    float d  = mB - mA;
    float m  = mA + d * (nBf * invT);
    float s  = sA + sB + d * d * (nAf * nBf * invT);
    int   nn = nnA + nnB;

    size_t base = (size_t)B * (size_t)CHW;
    out[base + p]                    = m;
    out[base + (size_t)CHW + p]      = s;
    out[base + 2 * (size_t)CHW + p]  = (float)nn;
    if (p == 0) {
        out[base + 3 * (size_t)CHW] = (float)(n0 + B);
    }
}

extern "C" void kernel_launch(void* const* d_in, const int* in_sizes, int n_in,
                              void* d_out, int out_size)
{
    const float* x  = (const float*)d_in[0];
    const float* m  = (const float*)d_in[1];
    const float* s  = (const float*)d_in[2];
    const int*   nn = (const int*)d_in[3];
    const int*   n  = (const int*)d_in[4];
    float* out = (float*)d_out;

    const int CHW = in_sizes[1];          // 262144
    const int B   = in_sizes[0] / CHW;    // 256

    const int threads = 128;
    const int blocks = (CHW + threads - 1) / threads;  // 2048
    welford_kernel_2s<<<blocks, threads>>>(x, m, s, nn, n, out, B, CHW);
}